// round 15
// baseline (speedup 1.0000x reference)
#include <cuda_runtime.h>
#include <cuda_bf16.h>
#include <math.h>
#include <stdint.h>

#define BB 2
#define QL 1024
#define ML 1024
#define KL 2048
#define EE 1024
#define HH 16
#define DH 64
#define FF 4096

typedef __nv_bfloat16 bf16;

// ---------------- scratch (static device globals) ---------------------------
__device__ float g_ao [BB*QL*EE];
__device__ float g_ao2[BB*QL*EE];
__device__ float g_x  [BB*QL*EE];
__device__ float g_y  [BB*QL*EE];
__device__ float g_y2 [BB*QL*EE];

__device__ bf16 g_cat_h[BB*KL*EE], g_cat_l[BB*KL*EE];
__device__ bf16 g_r_h  [KL*EE],    g_r_l  [KL*EE];
__device__ bf16 g_q_h  [BB*QL*EE], g_q_l  [BB*QL*EE];
__device__ bf16 g_k_h  [BB*KL*EE], g_k_l  [BB*KL*EE];
__device__ bf16 g_v_h  [BB*KL*EE], g_v_l  [BB*KL*EE];
__device__ bf16 g_rpj_h[KL*EE],    g_rpj_l[KL*EE];
__device__ bf16 g_att_h[BB*QL*EE], g_att_l[BB*QL*EE];
__device__ bf16 g_x_h  [BB*QL*EE], g_x_l  [BB*QL*EE];
__device__ bf16 g_hh_h [BB*QL*FF], g_hh_l [BB*QL*FF];
__device__ bf16 g_Wq_h[EE*EE], g_Wq_l[EE*EE];
__device__ bf16 g_Wk_h[EE*EE], g_Wk_l[EE*EE];
__device__ bf16 g_Wv_h[EE*EE], g_Wv_l[EE*EE];
__device__ bf16 g_Wr_h[EE*EE], g_Wr_l[EE*EE];
__device__ bf16 g_Wo_h[EE*EE], g_Wo_l[EE*EE];
__device__ bf16 g_W1_h[FF*EE], g_W1_l[FF*EE];
__device__ bf16 g_W2_h[EE*FF], g_W2_l[EE*FF];

// ---------------- persistent streams/events (host-side, created pre-run) ----
struct StreamSet {
    cudaStream_t s1, s2, s3;
    cudaEvent_t e0, eCat, eW, eV, eQ, eRg, eW12, eAtt, eWoB, eW1d, eW2B;
    StreamSet() {
        cudaStreamCreateWithFlags(&s1, cudaStreamNonBlocking);
        cudaStreamCreateWithFlags(&s2, cudaStreamNonBlocking);
        cudaStreamCreateWithFlags(&s3, cudaStreamNonBlocking);
        cudaEventCreateWithFlags(&e0,   cudaEventDisableTiming);
        cudaEventCreateWithFlags(&eCat, cudaEventDisableTiming);
        cudaEventCreateWithFlags(&eW,   cudaEventDisableTiming);
        cudaEventCreateWithFlags(&eV,   cudaEventDisableTiming);
        cudaEventCreateWithFlags(&eQ,   cudaEventDisableTiming);
        cudaEventCreateWithFlags(&eRg,  cudaEventDisableTiming);
        cudaEventCreateWithFlags(&eW12, cudaEventDisableTiming);
        cudaEventCreateWithFlags(&eAtt, cudaEventDisableTiming);
        cudaEventCreateWithFlags(&eWoB, cudaEventDisableTiming);
        cudaEventCreateWithFlags(&eW1d, cudaEventDisableTiming);
        cudaEventCreateWithFlags(&eW2B, cudaEventDisableTiming);
    }
};
static StreamSet g_ss;

// ---------------- helpers ----------------------------------------------------
__device__ __forceinline__ uint32_t smem_u32(const void* p) {
    uint32_t a;
    asm("{ .reg .u64 t; cvta.to.shared.u64 t, %1; cvt.u32.u64 %0, t; }"
        : "=r"(a) : "l"(p));
    return a;
}
__device__ __forceinline__ void split2(float v, bf16& h, bf16& l) {
    h = __float2bfloat16(v);
    l = __float2bfloat16(v - __bfloat162float(h));
}
__device__ __forceinline__ void ldsm4(uint32_t& r0, uint32_t& r1,
                                      uint32_t& r2, uint32_t& r3, uint32_t addr) {
    asm volatile("ldmatrix.sync.aligned.m8n8.x4.shared.b16 {%0,%1,%2,%3}, [%4];"
        : "=r"(r0), "=r"(r1), "=r"(r2), "=r"(r3) : "r"(addr));
}
__device__ __forceinline__ void ldsm4t(uint32_t& r0, uint32_t& r1,
                                       uint32_t& r2, uint32_t& r3, uint32_t addr) {
    asm volatile("ldmatrix.sync.aligned.m8n8.x4.trans.shared.b16 {%0,%1,%2,%3}, [%4];"
        : "=r"(r0), "=r"(r1), "=r"(r2), "=r"(r3) : "r"(addr));
}
__device__ __forceinline__ void mma16816(float* d, const uint32_t* a, const uint32_t* b) {
    asm volatile(
        "mma.sync.aligned.m16n8k16.row.col.f32.bf16.bf16.f32 "
        "{%0,%1,%2,%3}, {%4,%5,%6,%7}, {%8,%9}, {%0,%1,%2,%3};"
        : "+f"(d[0]), "+f"(d[1]), "+f"(d[2]), "+f"(d[3])
        : "r"(a[0]), "r"(a[1]), "r"(a[2]), "r"(a[3]), "r"(b[0]), "r"(b[1]));
}
__device__ __forceinline__ void cpa16(uint32_t d, const void* s) {
    asm volatile("cp.async.cg.shared.global [%0], [%1], 16;" :: "r"(d), "l"(s));
}
__device__ __forceinline__ void cpa16z(uint32_t d, const void* s, int sz) {
    asm volatile("cp.async.cg.shared.global [%0], [%1], 16, %2;"
                 :: "r"(d), "l"(s), "r"(sz));
}
#define CPA_COMMIT() asm volatile("cp.async.commit_group;")
template<int N> __device__ __forceinline__ void cpa_wait() {
    asm volatile("cp.async.wait_group %0;" :: "n"(N));
}

// ---------------- conversion kernels ----------------------------------------
__global__ __launch_bounds__(256) void concat_convert_kernel(
    const float* __restrict__ member, const float* __restrict__ w,
    bf16* __restrict__ dh, bf16* __restrict__ dl)
{
    int idx = blockIdx.x * 256 + threadIdx.x;
    int fidx = idx * 4;
    int b   = fidx / (KL*EE);
    int rem = fidx % (KL*EE);
    int s   = rem / EE;
    int e   = rem % EE;
    float4 v;
    if (s < ML) v = *(const float4*)&member[(size_t)(b*ML + s)*EE + e];
    else        v = *(const float4*)&w[(size_t)(b*QL + (s-ML))*EE + e];
    bf16 h0,l0,h1,l1,h2,l2,h3,l3;
    split2(v.x,h0,l0); split2(v.y,h1,l1); split2(v.z,h2,l2); split2(v.w,h3,l3);
    __nv_bfloat162 hp0, hp1, lp0, lp1;
    hp0.x=h0; hp0.y=h1; hp1.x=h2; hp1.y=h3;
    lp0.x=l0; lp0.y=l1; lp1.x=l2; lp1.y=l3;
    ((__nv_bfloat162*)dh)[idx*2]   = hp0; ((__nv_bfloat162*)dh)[idx*2+1] = hp1;
    ((__nv_bfloat162*)dl)[idx*2]   = lp0; ((__nv_bfloat162*)dl)[idx*2+1] = lp1;
}

__global__ __launch_bounds__(256) void convert_split_kernel(
    const float* __restrict__ s, bf16* __restrict__ dh, bf16* __restrict__ dl)
{
    int idx = blockIdx.x * 256 + threadIdx.x;
    float4 v = ((const float4*)s)[idx];
    bf16 h0,l0,h1,l1,h2,l2,h3,l3;
    split2(v.x,h0,l0); split2(v.y,h1,l1); split2(v.z,h2,l2); split2(v.w,h3,l3);
    __nv_bfloat162 hp0, hp1, lp0, lp1;
    hp0.x=h0; hp0.y=h1; hp1.x=h2; hp1.y=h3;
    lp0.x=l0; lp0.y=l1; lp1.x=l2; lp1.y=l3;
    ((__nv_bfloat162*)dh)[idx*2]   = hp0; ((__nv_bfloat162*)dh)[idx*2+1] = hp1;
    ((__nv_bfloat162*)dl)[idx*2]   = lp0; ((__nv_bfloat162*)dl)[idx*2+1] = lp1;
}

struct TC5 { const float* s[5]; bf16* dh[5]; bf16* dl[5]; };

__global__ void transpose_convert5_kernel(TC5 p)   // 5x square EExEE
{
    __shared__ float t[32][33];
    const float* s = p.s[blockIdx.z];
    bf16* dh = p.dh[blockIdx.z];
    bf16* dl = p.dl[blockIdx.z];
    int n0 = blockIdx.x * 32, k0 = blockIdx.y * 32;
    int tx = threadIdx.x, ty = threadIdx.y;
    #pragma unroll
    for (int i = 0; i < 4; i++)
        t[ty + i*8][tx] = s[(size_t)(k0 + ty + i*8)*EE + n0 + tx];
    __syncthreads();
    #pragma unroll
    for (int i = 0; i < 4; i++) {
        float v = t[tx][ty + i*8];
        bf16 h, l; split2(v, h, l);
        size_t o = (size_t)(n0 + ty + i*8)*EE + k0 + tx;
        dh[o] = h; dl[o] = l;
    }
}

__global__ void transpose_convert_kernel(
    const float* __restrict__ s, bf16* __restrict__ dh, bf16* __restrict__ dl,
    int K, int N)
{
    __shared__ float t[32][33];
    int n0 = blockIdx.x * 32, k0 = blockIdx.y * 32;
    int tx = threadIdx.x, ty = threadIdx.y;
    #pragma unroll
    for (int i = 0; i < 4; i++)
        t[ty + i*8][tx] = s[(size_t)(k0 + ty + i*8)*N + n0 + tx];
    __syncthreads();
    #pragma unroll
    for (int i = 0; i < 4; i++) {
        float v = t[tx][ty + i*8];
        bf16 h, l; split2(v, h, l);
        size_t o = (size_t)(n0 + ty + i*8)*K + k0 + tx;
        dh[o] = h; dl[o] = l;
    }
}

// ---------------- bf16x3 warp-MMA GEMM (cp.async double-buffered) -----------
#define SROW     40
#define OPELEMS  (128*SROW)
#define OPBYTES  (OPELEMS*2)
#define BUFELEMS (4*OPELEMS)
#define BUFBYTES (BUFELEMS*2)
#define GSM_TOTAL (2*BUFBYTES)

// EPI: 0 = fp32 store, 1 = relu + split bf16, 2 = split bf16
// REMAP: A rows remapped grow -> (grow/QL)*KL + ML + grow%QL  (Q-from-cat)
// LDA/LDB: compile-time row strides; 0 => use K (constant-folded, no extra regs)
template<int EPI, int REMAP, int LDA, int LDB>
__global__ __launch_bounds__(256, 2) void mma_gemm(
    const bf16* __restrict__ Ah, const bf16* __restrict__ Al,
    const bf16* __restrict__ Bh, const bf16* __restrict__ Bl,
    float* __restrict__ Cf, bf16* __restrict__ Ch, bf16* __restrict__ Cl,
    int M, int N, int K)
{
    extern __shared__ bf16 smem[];
    const int tid = threadIdx.x, wid = tid >> 5, lane = tid & 31;
    const int row0 = blockIdx.y * 128, col0 = blockIdx.x * 128;
    const int wm = wid & 1, wn = wid >> 1;
    const uint32_t sbase0 = smem_u32(smem);
    const int lda = LDA ? LDA : K;
    const int ldb = LDB ? LDB : K;

    float acc[4][4][4];
    #pragma unroll
    for (int mt = 0; mt < 4; mt++)
        #pragma unroll
        for (int nt = 0; nt < 4; nt++)
            #pragma unroll
            for (int u = 0; u < 4; u++) acc[mt][nt][u] = 0.f;

    const int nc = K >> 5;
    const int r0q = tid >> 2, c0q = (tid & 3) * 8;
    const int r1q = r0q + 64;

    size_t aR0, aR1;
    if (REMAP) {
        const int g0 = row0 + r0q, g1 = row0 + r1q;
        aR0 = ((size_t)(g0 >> 10)*KL + ML + (g0 & 1023)) * (size_t)lda;
        aR1 = ((size_t)(g1 >> 10)*KL + ML + (g1 & 1023)) * (size_t)lda;
    } else {
        aR0 = (size_t)(row0 + r0q) * lda;
        aR1 = (size_t)(row0 + r1q) * lda;
    }
    const size_t bR0 = (size_t)(col0 + r0q) * ldb;
    const size_t bR1 = (size_t)(col0 + r1q) * ldb;
    const uint32_t s0b = (uint32_t)(r0q*80 + c0q*2);
    const uint32_t s1b = (uint32_t)(r1q*80 + c0q*2);

    auto issue = [&](int c) {
        const uint32_t d = sbase0 + (uint32_t)(c & 1) * BUFBYTES;
        const size_t k0 = (size_t)(c * 32) + c0q;
        cpa16(d + s0b,             Ah + aR0 + k0);
        cpa16(d + s0b + OPBYTES,   Al + aR0 + k0);
        cpa16(d + s0b + 2*OPBYTES, Bh + bR0 + k0);
        cpa16(d + s0b + 3*OPBYTES, Bl + bR0 + k0);
        cpa16(d + s1b,             Ah + aR1 + k0);
        cpa16(d + s1b + OPBYTES,   Al + aR1 + k0);
        cpa16(d + s1b + 2*OPBYTES, Bh + bR1 + k0);
        cpa16(d + s1b + 3*OPBYTES, Bl + bR1 + k0);
        CPA_COMMIT();
    };

    issue(0);

    const uint32_t a_row_off = (uint32_t)(wm*64 + (lane & 15)) * 80
                             + (uint32_t)(lane >> 4) * 16;
    const uint32_t b_row_off = 2*OPBYTES
                             + (uint32_t)(wn*32 + (lane & 7) + ((lane >> 4) & 1)*8) * 80
                             + (uint32_t)((lane >> 3) & 1) * 16;

    for (int c = 0; c < nc; c++) {
        cpa_wait<0>();
        __syncthreads();
        if (c + 1 < nc) issue(c + 1);

        const uint32_t sb = sbase0 + (uint32_t)(c & 1) * BUFBYTES;
        #pragma unroll
        for (int ks = 0; ks < 2; ks++) {
            uint32_t ah[4][4], al[4][4], bh[4][2], bl[4][2];
            const uint32_t abase = sb + a_row_off + ks*32;
            #pragma unroll
            for (int mt = 0; mt < 4; mt++) {
                const uint32_t ad = abase + mt*(16*80);
                ldsm4(ah[mt][0], ah[mt][1], ah[mt][2], ah[mt][3], ad);
                ldsm4(al[mt][0], al[mt][1], al[mt][2], al[mt][3], ad + OPBYTES);
            }
            const uint32_t bbase = sb + b_row_off + ks*32;
            #pragma unroll
            for (int p = 0; p < 2; p++) {
                const uint32_t bd = bbase + p*(16*80);
                ldsm4(bh[2*p][0], bh[2*p][1], bh[2*p+1][0], bh[2*p+1][1], bd);
                ldsm4(bl[2*p][0], bl[2*p][1], bl[2*p+1][0], bl[2*p+1][1], bd + OPBYTES);
            }
            #pragma unroll
            for (int mt = 0; mt < 4; mt++)
                #pragma unroll
                for (int nt = 0; nt < 4; nt++) {
                    mma16816(acc[mt][nt], ah[mt], bh[nt]);
                    mma16816(acc[mt][nt], ah[mt], bl[nt]);
                    mma16816(acc[mt][nt], al[mt], bh[nt]);
                }
        }
    }

    const int er = lane >> 2, ec = (lane & 3) * 2;
    #pragma unroll
    for (int mt = 0; mt < 4; mt++) {
        #pragma unroll
        for (int nt = 0; nt < 4; nt++) {
            const int grow = row0 + wm*64 + mt*16 + er;
            const int gcol = col0 + wn*32 + nt*8 + ec;
            if (EPI == 0) {
                *(float2*)&Cf[(size_t)grow*N + gcol] =
                    make_float2(acc[mt][nt][0], acc[mt][nt][1]);
                *(float2*)&Cf[(size_t)(grow+8)*N + gcol] =
                    make_float2(acc[mt][nt][2], acc[mt][nt][3]);
            } else {
                float f0 = acc[mt][nt][0], f1 = acc[mt][nt][1];
                float f2 = acc[mt][nt][2], f3 = acc[mt][nt][3];
                if (EPI == 1) {
                    f0 = fmaxf(f0, 0.f); f1 = fmaxf(f1, 0.f);
                    f2 = fmaxf(f2, 0.f); f3 = fmaxf(f3, 0.f);
                }
                bf16 h0,l0,h1,l1,h2,l2,h3,l3;
                split2(f0,h0,l0); split2(f1,h1,l1);
                split2(f2,h2,l2); split2(f3,h3,l3);
                __nv_bfloat162 hp0, lp0, hp1, lp1;
                hp0.x=h0; hp0.y=h1; lp0.x=l0; lp0.y=l1;
                hp1.x=h2; hp1.y=h3; lp1.x=l2; lp1.y=l3;
                *(__nv_bfloat162*)&Ch[(size_t)grow*N + gcol]     = hp0;
                *(__nv_bfloat162*)&Cl[(size_t)grow*N + gcol]     = lp0;
                *(__nv_bfloat162*)&Ch[(size_t)(grow+8)*N + gcol] = hp1;
                *(__nv_bfloat162*)&Cl[(size_t)(grow+8)*N + gcol] = lp1;
            }
        }
    }
}

// ---------------- MMA flash attention: 8 warps (pair-split columns) ---------
#define ASTR 144
#define A_QWH 0
#define A_QWL 9216
#define A_QRH 18432
#define A_QRL 27648
#define A_STG 36864
#define S_KH  0
#define S_KL  9216
#define S_VH  18432
#define S_VL  27648
#define S_RH  36864
#define S_RL  46080
#define STG_SZ 55296
#define A_SCR (A_STG + 2*STG_SZ)       // 147456
#define W_BDW 0
#define W_PH  8448
#define W_PL  10752
#define WSCR_SZ 13056
#define A_EXCH (A_SCR + 4*WSCR_SZ)     // 199680
#define A_TOT (A_EXCH + 1024)          // 200704

// one 32-col slice of a 64-col BDW half: D = Qr @ Rstage^T, this warp covers
// cols [pb + cs*32, pb + cs*32 + 32)
__device__ __forceinline__ void bdw_half(
    char* sm, uint32_t sb, uint32_t rbase, int pb, int cs,
    uint32_t aoff, uint32_t boff, uint32_t wscr, int er, int ec)
{
    float D[4][4];
    #pragma unroll
    for (int nt = 0; nt < 4; nt++)
        #pragma unroll
        for (int u = 0; u < 4; u++) D[nt][u] = 0.f;
    #pragma unroll
    for (int ks = 0; ks < 4; ks++) {
        uint32_t arh[4], arl[4];
        ldsm4(arh[0], arh[1], arh[2], arh[3], sb + A_QRH + aoff + ks*32);
        ldsm4(arl[0], arl[1], arl[2], arl[3], sb + A_QRL + aoff + ks*32);
        #pragma unroll
        for (int p2 = 0; p2 < 2; p2++) {
            const int p = cs*2 + p2;
            uint32_t bh4[4], bl4[4];
            const uint32_t ra = rbase + boff + (uint32_t)(p*16)*ASTR + ks*32;
            ldsm4(bh4[0], bh4[1], bh4[2], bh4[3], ra);
            ldsm4(bl4[0], bl4[1], bl4[2], bl4[3], ra + (S_RL - S_RH));
            mma16816(D[2*p2],   arh, bh4);   mma16816(D[2*p2],   arh, bl4);
            mma16816(D[2*p2],   arl, bh4);
            mma16816(D[2*p2+1], arh, bh4+2); mma16816(D[2*p2+1], arh, bl4+2);
            mma16816(D[2*p2+1], arl, bh4+2);
        }
    }
    float* bdw = (float*)(sm + wscr + W_BDW);
    #pragma unroll
    for (int nt = 0; nt < 4; nt++) {
        const int c = pb + cs*32 + nt*8 + ec;
        bdw[er*132 + c]       = D[nt][0];
        bdw[er*132 + c + 1]   = D[nt][1];
        bdw[(er+8)*132 + c]   = D[nt][2];
        bdw[(er+8)*132 + c+1] = D[nt][3];
    }
}

__global__ __launch_bounds__(256) void attn_mma_kernel(
    const bf16* __restrict__ Qh, const bf16* __restrict__ Ql,
    const bf16* __restrict__ Kh, const bf16* __restrict__ Kl,
    const bf16* __restrict__ Vh, const bf16* __restrict__ Vl,
    const bf16* __restrict__ Rh, const bf16* __restrict__ Rl,
    const float* __restrict__ rwb, const float* __restrict__ rrb,
    bf16* __restrict__ OHp, bf16* __restrict__ OLp)
{
    extern __shared__ char sm[];
    const uint32_t sb = smem_u32(sm);
    const int i0 = blockIdx.x * 64;
    const int h  = blockIdx.y, b = blockIdx.z;
    const int tid = threadIdx.x, w = tid >> 5, lane = tid & 31;
    const int rg = w & 3;        // row group (rows rg*16 .. rg*16+15)
    const int cs = w >> 2;       // column side (0: cols 0-31, 1: cols 32-63)

    // ---- load Q, add biases, split, store both variants (256 threads) ----
    #pragma unroll
    for (int it = 0; it < 2; it++) {
        int idx = tid + it*256;
        int row = idx >> 3, c8 = (idx & 7) * 8;
        const size_t g = (size_t)(b*QL + i0 + row)*EE + h*DH + c8;
        union { uint4 u; bf16 e[8]; } uh, ul;
        uh.u = *(const uint4*)(Qh + g);
        ul.u = *(const uint4*)(Ql + g);
        bf16* qwh = (bf16*)(sm + A_QWH + row*ASTR) + c8;
        bf16* qwl = (bf16*)(sm + A_QWL + row*ASTR) + c8;
        bf16* qrh = (bf16*)(sm + A_QRH + row*ASTR) + c8;
        bf16* qrl = (bf16*)(sm + A_QRL + row*ASTR) + c8;
        #pragma unroll
        for (int e = 0; e < 8; e++) {
            float q = __bfloat162float(uh.e[e]) + __bfloat162float(ul.e[e]);
            bf16 hh, ll;
            split2(q + rwb[h*DH + c8 + e], hh, ll); qwh[e] = hh; qwl[e] = ll;
            split2(q + rrb[h*DH + c8 + e], hh, ll); qrh[e] = hh; qrl[e] = ll;
        }
    }

    float O[4][4];
    #pragma unroll
    for (int nt = 0; nt < 4; nt++)
        #pragma unroll
        for (int u = 0; u < 4; u++) O[nt][u] = 0.f;
    float m_i[2] = {-INFINITY, -INFINITY}, l_i[2] = {0.f, 0.f};

    const uint32_t aoff = (uint32_t)(rg*16 + (lane&15))*ASTR + ((lane>>4)&1)*16;
    const uint32_t boff = (uint32_t)((lane&7) + ((lane>>4)&1)*8)*ASTR + ((lane>>3)&1)*16;
    const uint32_t voff = (uint32_t)((lane&7) + ((lane>>3)&1)*8)*ASTR + ((lane>>4)&1)*16;
    const uint32_t poff = (uint32_t)(lane&15)*ASTR + ((lane>>4)&1)*16;
    const uint32_t wscr = A_SCR + rg*WSCR_SZ;
    float* exch = (float*)(sm + A_EXCH) + rg*64;   // [side*32 + slot]
    const int er = lane >> 2, ec = (lane & 3) * 2;
    const int lr0 = rg*16 + er, lr1 = lr0 + 8;
    const int ig0 = i0 + lr0, ig1 = i0 + lr1;

    int njt = (i0 + 63 + ML)/64 + 1;
    if (njt > KL/64) njt = KL/64;
    const int rorg = 960 - i0;   // absolute r-index of physical BDW slot 0

    const int ldrow = tid >> 3, ldc8 = (tid & 7) * 8;   // ldrow in [0,32)

    // ---- prologue: R_low -> stage1 R area; tile0 -> stage0 ----
    #pragma unroll
    for (int it = 0; it < 2; it++) {
        int row = ldrow + it*32;
        int dg = rorg + row;                           // >= 0 always (i0<=960)
        const size_t g = (size_t)dg*EE + h*DH + ldc8;
        uint32_t d = sb + A_STG + STG_SZ + S_RH + row*ASTR + ldc8*2;
        cpa16(d,                 Rh + g);
        cpa16(d + (S_RL - S_RH), Rl + g);
    }
    {
        const uint32_t stg = sb + A_STG;               // stage 0
        #pragma unroll
        for (int it = 0; it < 2; it++) {
            int row = ldrow + it*32;
            const size_t g = (size_t)(b*KL + row)*EE + h*DH + ldc8;
            const uint32_t so = row*ASTR + ldc8*2;
            cpa16(stg + S_KH + so, Kh + g);
            cpa16(stg + S_KL + so, Kl + g);
            cpa16(stg + S_VH + so, Vh + g);
            cpa16(stg + S_VL + so, Vl + g);
            int dg = rorg + 64 + row;
            int ok = dg < KL;
            const size_t gr = (size_t)(ok ? dg : 0)*EE + h*DH + ldc8;
            cpa16z(stg + S_RH + so, Rh + gr, ok ? 16 : 0);
            cpa16z(stg + S_RL + so, Rl + gr, ok ? 16 : 0);
        }
    }
    CPA_COMMIT();
    cpa_wait<0>();
    __syncthreads();

    // prologue BDW (phys cols [0,64), from stage1 R); each warp does 32 cols
    bdw_half(sm, sb, sb + A_STG + STG_SZ + S_RH, 0, cs, aoff, boff, wscr, er, ec);

    for (int jt = 0; jt < njt; jt++) {
        const int j0 = jt * 64;
        __syncthreads();                       // all warps done with jt-1 (+ prologue BDW)
        if (jt + 1 < njt) {
            const uint32_t stg = sb + A_STG + ((jt+1)&1)*STG_SZ;
            const int jn = (jt+1)*64;
            #pragma unroll
            for (int it = 0; it < 2; it++) {
                int row = ldrow + it*32;
                const size_t g = (size_t)(b*KL + jn + row)*EE + h*DH + ldc8;
                const uint32_t so = row*ASTR + ldc8*2;
                cpa16(stg + S_KH + so, Kh + g);
                cpa16(stg + S_KL + so, Kl + g);
                cpa16(stg + S_VH + so, Vh + g);
                cpa16(stg + S_VL + so, Vl + g);
                int dg = rorg + 64*(jt+2) + row;
                int ok = dg < KL;
                const size_t gr = (size_t)(ok ? dg : 0)*EE + h*DH + ldc8;
                cpa16z(stg + S_RH + so, Rh + gr, ok ? 16 : 0);
                cpa16z(stg + S_RL + so, Rl + gr, ok ? 16 : 0);
            }
            CPA_COMMIT();
            cpa_wait<1>();
        } else {
            cpa_wait<0>();
        }
        __syncthreads();

        const uint32_t stg = sb + A_STG + (jt&1)*STG_SZ;

        // ---- BDW new half (this warp: 32 of the 64 cols) ----
        bdw_half(sm, sb, stg + S_RH, (jt&1) ? 0 : 64, cs, aoff, boff, wscr, er, ec);

        // ---- AC = Qw @ K^T (own 32 cols) ----
        float S[4][4];
        #pragma unroll
        for (int nt = 0; nt < 4; nt++)
            #pragma unroll
            for (int u = 0; u < 4; u++) S[nt][u] = 0.f;
        #pragma unroll
        for (int ks = 0; ks < 4; ks++) {
            uint32_t awh[4], awl[4];
            ldsm4(awh[0], awh[1], awh[2], awh[3], sb + A_QWH + aoff + ks*32);
            ldsm4(awl[0], awl[1], awl[2], awl[3], sb + A_QWL + aoff + ks*32);
            #pragma unroll
            for (int p2 = 0; p2 < 2; p2++) {
                const int p = cs*2 + p2;
                uint32_t bh4[4], bl4[4];
                const uint32_t ka = stg + S_KH + boff + (uint32_t)(p*16)*ASTR + ks*32;
                ldsm4(bh4[0], bh4[1], bh4[2], bh4[3], ka);
                ldsm4(bl4[0], bl4[1], bl4[2], bl4[3], ka + (S_KL - S_KH));
                mma16816(S[2*p2],   awh, bh4);   mma16816(S[2*p2],   awh, bl4);
                mma16816(S[2*p2],   awl, bh4);
                mma16816(S[2*p2+1], awh, bh4+2); mma16816(S[2*p2+1], awh, bl4+2);
                mma16816(S[2*p2+1], awl, bh4+2);
            }
        }
        __syncthreads();   // BDW halves complete (both warps of pair)

        // ---- gather rolling BDW diagonal, mask+scale, local max ----
        const float* bdw = (const float*)(sm + wscr + W_BDW);
        const int phase = (jt & 1) * 64;
        float mx0 = -INFINITY, mx1 = -INFINITY;
        #pragma unroll
        for (int nt = 0; nt < 4; nt++) {
            const int c = cs*32 + nt*8 + ec;
            float s00 = S[nt][0] + bdw[er*132     + ((c   - lr0 + 63 + phase) & 127)];
            float s01 = S[nt][1] + bdw[er*132     + ((c+1 - lr0 + 63 + phase) & 127)];
            float s10 = S[nt][2] + bdw[(er+8)*132 + ((c   - lr1 + 63 + phase) & 127)];
            float s11 = S[nt][3] + bdw[(er+8)*132 + ((c+1 - lr1 + 63 + phase) & 127)];
            const int jg = j0 + c;
            s00 = (jg   > ig0 + ML) ? -1e30f : s00 * 0.03125f;
            s01 = (jg+1 > ig0 + ML) ? -1e30f : s01 * 0.03125f;
            s10 = (jg   > ig1 + ML) ? -1e30f : s10 * 0.03125f;
            s11 = (jg+1 > ig1 + ML) ? -1e30f : s11 * 0.03125f;
            S[nt][0] = s00; S[nt][1] = s01; S[nt][2] = s10; S[nt][3] = s11;
            mx0 = fmaxf(mx0, fmaxf(s00, s01));
            mx1 = fmaxf(mx1, fmaxf(s10, s11));
        }
        mx0 = fmaxf(mx0, __shfl_xor_sync(0xffffffffu, mx0, 1));
        mx0 = fmaxf(mx0, __shfl_xor_sync(0xffffffffu, mx0, 2));
        mx1 = fmaxf(mx1, __shfl_xor_sync(0xffffffffu, mx1, 1));
        mx1 = fmaxf(mx1, __shfl_xor_sync(0xffffffffu, mx1, 2));
        if ((lane & 3) == 0) {
            exch[cs*32 + er]     = mx0;
            exch[cs*32 + 8 + er] = mx1;
        }
        __syncthreads();
        const float mo0 = exch[(1 - cs)*32 + er];
        const float mo1 = exch[(1 - cs)*32 + 8 + er];
        const float mn0 = fmaxf(m_i[0], fmaxf(mx0, mo0));
        const float mn1 = fmaxf(m_i[1], fmaxf(mx1, mo1));
        const float sf0 = __expf(m_i[0] - mn0), sf1 = __expf(m_i[1] - mn1);
        m_i[0] = mn0; m_i[1] = mn1;

        bf16* pph = (bf16*)(sm + wscr + W_PH);
        bf16* ppl = (bf16*)(sm + wscr + W_PL);
        float ps0 = 0.f, ps1 = 0.f;
        #pragma unroll
        for (int nt = 0; nt < 4; nt++) {
            const int c = cs*32 + nt*8 + ec;
            float p00 = __expf(S[nt][0] - mn0);
            float p01 = __expf(S[nt][1] - mn0);
            float p10 = __expf(S[nt][2] - mn1);
            float p11 = __expf(S[nt][3] - mn1);
            ps0 += p00 + p01; ps1 += p10 + p11;
            bf16 h0,l0,h1,l1;
            __nv_bfloat162 hp, lp;
            split2(p00,h0,l0); split2(p01,h1,l1);
            hp.x=h0; hp.y=h1; lp.x=l0; lp.y=l1;
            *(__nv_bfloat162*)(pph + er*72 + c) = hp;
            *(__nv_bfloat162*)(ppl + er*72 + c) = lp;
            split2(p10,h0,l0); split2(p11,h1,l1);
            hp.x=h0; hp.y=h1; lp.x=l0; lp.y=l1;
            *(__nv_bfloat162*)(pph + (er+8)*72 + c) = hp;
            *(__nv_bfloat162*)(ppl + (er+8)*72 + c) = lp;
        }
        ps0 += __shfl_xor_sync(0xffffffffu, ps0, 1);
        ps0 += __shfl_xor_sync(0xffffffffu, ps0, 2);
        ps1 += __shfl_xor_sync(0xffffffffu, ps1, 1);
        ps1 += __shfl_xor_sync(0xffffffffu, ps1, 2);
        if ((lane & 3) == 0) {
            exch[cs*32 + 16 + er] = ps0;
            exch[cs*32 + 24 + er] = ps1;
        }
        __syncthreads();   // P complete + ps exchanged
        const float po0 = exch[(1 - cs)*32 + 16 + er];
        const float po1 = exch[(1 - cs)*32 + 24 + er];
        l_i[0] = l_i[0]*sf0 + ps0 + po0;
        l_i[1] = l_i[1]*sf1 + ps1 + po1;
        #pragma unroll
        for (int nt = 0; nt < 4; nt++) {
            O[nt][0] *= sf0; O[nt][1] *= sf0;
            O[nt][2] *= sf1; O[nt][3] *= sf1;
        }

        // ---- O += P @ V (own 32 dh cols; all 64 P cols from shared scratch) ----
        #pragma unroll
        for (int ks = 0; ks < 4; ks++) {
            uint32_t ph4[4], pl4[4];
            ldsm4(ph4[0], ph4[1], ph4[2], ph4[3], sb + wscr + W_PH + poff + ks*32);
            ldsm4(pl4[0], pl4[1], pl4[2], pl4[3], sb + wscr + W_PL + poff + ks*32);
            #pragma unroll
            for (int p2 = 0; p2 < 2; p2++) {
                const int p = cs*2 + p2;
                uint32_t vh4[4], vl4[4];
                const uint32_t va = stg + S_VH + voff + (uint32_t)(ks*16)*ASTR + p*32;
                ldsm4t(vh4[0], vh4[1], vh4[2], vh4[3], va);
                ldsm4t(vl4[0], vl4[1], vl4[2], vl4[3], va + (S_VL - S_VH));
                mma16816(O[2*p2],   ph4, vh4);   mma16816(O[2*p2],   ph4, vl4);
                mma16816(O[2*p2],   pl4, vh4);
                mma16816(O[2*p2+1], ph4, vh4+2); mma16816(O[2*p2+1], ph4, vl4+2);
                mma16816(O[2*p2+1], pl4, vh4+2);
            }
        }
    }

    // ---- epilogue: normalize + split store (own 32 dh cols) ----
    const float inv0 = 1.0f / l_i[0], inv1 = 1.0f / l_i[1];
    #pragma unroll
    for (int nt = 0; nt < 4; nt++) {
        const int c = cs*32 + nt*8 + ec;
        const size_t g0 = (size_t)(b*QL + ig0)*EE + h*DH + c;
        const size_t g1 = (size_t)(b*QL + ig1)*EE + h*DH + c;
        bf16 h0,l0,h1,l1;
        __nv_bfloat162 hp, lp;
        split2(O[nt][0]*inv0, h0, l0); split2(O[nt][1]*inv0, h1, l1);
        hp.x=h0; hp.y=h1; lp.x=l0; lp.y=l1;
        *(__nv_bfloat162*)(OHp + g0) = hp;
        *(__nv_bfloat162*)(OLp + g0) = lp;
        split2(O[nt][2]*inv1, h0, l0); split2(O[nt][3]*inv1, h1, l1);
        hp.x=h0; hp.y=h1; lp.x=l0; lp.y=l1;
        *(__nv_bfloat162*)(OHp + g1) = hp;
        *(__nv_bfloat162*)(OLp + g1) = lp;
    }
}

// ---------------- residual add + LayerNorm ----------------------------------
// TWO=1: sums a + a2 (split-K partials) + residual
template<int WB, int TWO>
__global__ __launch_bounds__(256) void add_ln_kernel(
    const float* __restrict__ a, const float* __restrict__ a2,
    const float* __restrict__ res,
    const float* __restrict__ g, const float* __restrict__ bt,
    float* __restrict__ out, bf16* __restrict__ oh, bf16* __restrict__ ol)
{
    __shared__ float red[256];
    const int row = blockIdx.x;
    const int tid = threadIdx.x;
    const size_t base = (size_t)row * EE;

    float v[4];
    #pragma unroll
    for (int u = 0; u < 4; u++) {
        v[u] = a[base + u*256 + tid] + res[base + u*256 + tid];
        if (TWO) v[u] += a2[base + u*256 + tid];
    }

    float s = v[0] + v[1] + v[2] + v[3];
    red[tid] = s; __syncthreads();
    for (int off = 128; off > 0; off >>= 1) {
        if (tid < off) red[tid] += red[tid + off];
        __syncthreads();
    }
    const float mu = red[0] * (1.0f / EE);
    __syncthreads();

    float d = 0.f;
    #pragma unroll
    for (int u = 0; u < 4; u++) { float t = v[u] - mu; d += t*t; }
    red[tid] = d; __syncthreads();
    for (int off = 128; off > 0; off >>= 1) {
        if (tid < off) red[tid] += red[tid + off];
        __syncthreads();
    }
    const float rs = rsqrtf(red[0] * (1.0f / EE) + 1e-3f);

    #pragma unroll
    for (int u = 0; u < 4; u++) {
        int c = u*256 + tid;
        float o = (v[u] - mu) * rs * g[c] + bt[c];
        out[base + c] = o;
        if (WB) {
            bf16 hh_, ll_; split2(o, hh_, ll_);
            oh[base + c] = hh_; ol[base + c] = ll_;
        }
    }
}

// ---------------- launch ----------------------------------------------------
extern "C" void kernel_launch(void* const* d_in, const int* in_sizes, int n_in,
                              void* d_out, int out_size)
{
    const float* w      = (const float*)d_in[0];
    const float* r      = (const float*)d_in[1];
    const float* member = (const float*)d_in[2];
    const float* Wq     = (const float*)d_in[4];
    const float* Wk     = (const float*)d_in[5];
    const float* Wv     = (const float*)d_in[6];
    const float* Wr     = (const float*)d_in[7];
    const float* Wo     = (const float*)d_in[8];
    const float* rwb    = (const float*)d_in[9];
    const float* rrb    = (const float*)d_in[10];
    const float* ln1g   = (const float*)d_in[11];
    const float* ln1b   = (const float*)d_in[12];
    const float* W1     = (const float*)d_in[13];
    const float* W2     = (const float*)d_in[14];
    const float* ln2g   = (const float*)d_in[15];
    const float* ln2b   = (const float*)d_in[16];
    float* out = (float*)d_out;

    float *ao,*ao2,*x,*y,*y2;
    cudaGetSymbolAddress((void**)&ao,  g_ao);
    cudaGetSymbolAddress((void**)&ao2, g_ao2);
    cudaGetSymbolAddress((void**)&x,   g_x);
    cudaGetSymbolAddress((void**)&y,   g_y);
    cudaGetSymbolAddress((void**)&y2,  g_y2);
    bf16 *cath,*catl,*rih,*ril,*atth,*attl,*xh,*xl,*hhh,*hhl;
    bf16 *qph,*qpl,*kph,*kpl,*vph,*vpl,*rph,*rpl;
    bf16 *wqh,*wql,*wkh,*wkl,*wvh,*wvl,*wrh,*wrl,*woh,*wol,*w1h,*w1l,*w2h,*w2l;
    cudaGetSymbolAddress((void**)&cath, g_cat_h); cudaGetSymbolAddress((void**)&catl, g_cat_l);
    cudaGetSymbolAddress((void**)&rih,  g_r_h);   cudaGetSymbolAddress((void**)&ril,  g_r_l);
    cudaGetSymbolAddress((void**)&qph,  g_q_h);   cudaGetSymbolAddress((void**)&qpl,  g_q_l);
    cudaGetSymbolAddress((void**)&kph,  g_k_h);   cudaGetSymbolAddress((void**)&kpl,  g_k_l);
    cudaGetSymbolAddress((void**)&vph,  g_v_h);   cudaGetSymbolAddress((void**)&vpl,  g_v_l);
    cudaGetSymbolAddress((void**)&rph,  g_rpj_h); cudaGetSymbolAddress((void**)&rpl,  g_rpj_l);
    cudaGetSymbolAddress((void**)&atth, g_att_h); cudaGetSymbolAddress((void**)&attl, g_att_l);
    cudaGetSymbolAddress((void**)&xh,   g_x_h);   cudaGetSymbolAddress((void**)&xl,   g_x_l);
    cudaGetSymbolAddress((void**)&hhh,  g_hh_h);  cudaGetSymbolAddress((void**)&hhl,  g_hh_l);
    cudaGetSymbolAddress((void**)&wqh,  g_Wq_h);  cudaGetSymbolAddress((void**)&wql,  g_Wq_l);
    cudaGetSymbolAddress((void**)&wkh,  g_Wk_h);  cudaGetSymbolAddress((void**)&wkl,  g_Wk_l);
    cudaGetSymbolAddress((void**)&wvh,  g_Wv_h);  cudaGetSymbolAddress((void**)&wvl,  g_Wv_l);
    cudaGetSymbolAddress((void**)&wrh,  g_Wr_h);  cudaGetSymbolAddress((void**)&wrl,  g_Wr_l);
    cudaGetSymbolAddress((void**)&woh,  g_Wo_h);  cudaGetSymbolAddress((void**)&wol,  g_Wo_l);
    cudaGetSymbolAddress((void**)&w1h,  g_W1_h);  cudaGetSymbolAddress((void**)&w1l,  g_W1_l);
    cudaGetSymbolAddress((void**)&w2h,  g_W2_h);  cudaGetSymbolAddress((void**)&w2l,  g_W2_l);

    cudaFuncSetAttribute((const void*)mma_gemm<0,0,0,0>,   cudaFuncAttributeMaxDynamicSharedMemorySize, GSM_TOTAL);
    cudaFuncSetAttribute((const void*)mma_gemm<1,0,0,0>,   cudaFuncAttributeMaxDynamicSharedMemorySize, GSM_TOTAL);
    cudaFuncSetAttribute((const void*)mma_gemm<2,0,0,0>,   cudaFuncAttributeMaxDynamicSharedMemorySize, GSM_TOTAL);
    cudaFuncSetAttribute((const void*)mma_gemm<2,1,0,0>,   cudaFuncAttributeMaxDynamicSharedMemorySize, GSM_TOTAL);
    cudaFuncSetAttribute((const void*)mma_gemm<0,0,EE,EE>, cudaFuncAttributeMaxDynamicSharedMemorySize, GSM_TOTAL);
    cudaFuncSetAttribute((const void*)mma_gemm<0,0,FF,FF>, cudaFuncAttributeMaxDynamicSharedMemorySize, GSM_TOTAL);
    cudaFuncSetAttribute((const void*)attn_mma_kernel, cudaFuncAttributeMaxDynamicSharedMemorySize, A_TOT);

    cudaStream_t s1 = g_ss.s1, s2 = g_ss.s2, s3 = g_ss.s3;

    // fork side streams into the capture
    cudaEventRecord(g_ss.e0, 0);
    cudaStreamWaitEvent(s1, g_ss.e0, 0);
    cudaStreamWaitEvent(s2, g_ss.e0, 0);
    cudaStreamWaitEvent(s3, g_ss.e0, 0);

    // stream 0: concat conversion
    concat_convert_kernel<<<BB*KL*EE/4/256, 256>>>(member, w, cath, catl);
    cudaEventRecord(g_ss.eCat, 0);

    // s1: square weight transposes
    {
        TC5 p;
        p.s[0]=Wq; p.dh[0]=wqh; p.dl[0]=wql;
        p.s[1]=Wk; p.dh[1]=wkh; p.dl[1]=wkl;
        p.s[2]=Wv; p.dh[2]=wvh; p.dl[2]=wvl;
        p.s[3]=Wr; p.dh[3]=wrh; p.dl[3]=wrl;
        p.s[4]=Wo; p.dh[4]=woh; p.dl[4]=wol;
        transpose_convert5_kernel<<<dim3(EE/32, EE/32, 5), dim3(32,8), 0, s1>>>(p);
    }
    cudaEventRecord(g_ss.eW, s1);

    // s2: r conversion, then FFN weight transposes
    convert_split_kernel<<<KL*EE/4/256, 256, 0, s2>>>(r, rih, ril);
    transpose_convert_kernel<<<dim3(FF/32, EE/32), dim3(32,8), 0, s2>>>(W1, w1h, w1l, EE, FF);
    transpose_convert_kernel<<<dim3(EE/32, FF/32), dim3(32,8), 0, s2>>>(W2, w2h, w2l, FF, EE);
    cudaEventRecord(g_ss.eW12, s2);

    // projections spread over 4 streams
    cudaStreamWaitEvent(0, g_ss.eW, 0);
    mma_gemm<2,0,0,0><<<dim3(EE/128, (BB*KL)/128), 256, GSM_TOTAL>>>(
        cath, catl, wkh, wkl, nullptr, kph, kpl, BB*KL, EE, EE);

    cudaStreamWaitEvent(s1, g_ss.eCat, 0);
    mma_gemm<2,0,0,0><<<dim3(EE/128, (BB*KL)/128), 256, GSM_TOTAL, s1>>>(
        cath, catl, wvh, wvl, nullptr, vph, vpl, BB*KL, EE, EE);
    cudaEventRecord(g_ss.eV, s1);

    cudaStreamWaitEvent(s3, g_ss.eCat, 0);
    cudaStreamWaitEvent(s3, g_ss.eW, 0);
    mma_gemm<2,1,0,0><<<dim3(EE/128, (BB*QL)/128), 256, GSM_TOTAL, s3>>>(
        cath, catl, wqh, wql, nullptr, qph, qpl, BB*QL, EE, EE);
    cudaEventRecord(g_ss.eQ, s3);

    cudaStreamWaitEvent(s2, g_ss.eW, 0);
    mma_gemm<2,0,0,0><<<dim3(EE/128, KL/128), 256, GSM_TOTAL, s2>>>(
        rih, ril, wrh, wrl, nullptr, rph, rpl, KL, EE, EE);
    cudaEventRecord(g_ss.eRg, s2);

    // join, then attention on stream 0 (8-warp pair-split version)
    cudaStreamWaitEvent(0, g_ss.eV, 0);
    cudaStreamWaitEvent(0, g_ss.eQ, 0);
    cudaStreamWaitEvent(0, g_ss.eRg, 0);
    attn_mma_kernel<<<dim3(QL/64, HH, BB), 256, A_TOT>>>(
        qph, qpl, kph, kpl, vph, vpl, rph, rpl, rwb, rrb, atth, attl);
    cudaEventRecord(g_ss.eAtt, 0);

    // output projection: split-K x2 across streams (full-chip occupancy)
    mma_gemm<0,0,EE,EE><<<dim3(EE/128, (BB*QL)/128), 256, GSM_TOTAL>>>(
        atth, attl, woh, wol, ao, nullptr, nullptr, BB*QL, EE, EE/2);
    cudaStreamWaitEvent(s1, g_ss.eAtt, 0);
    mma_gemm<0,0,EE,EE><<<dim3(EE/128, (BB*QL)/128), 256, GSM_TOTAL, s1>>>(
        atth + EE/2, attl + EE/2, woh + EE/2, wol + EE/2,
        ao2, nullptr, nullptr, BB*QL, EE, EE/2);
    cudaEventRecord(g_ss.eWoB, s1);
    cudaStreamWaitEvent(0, g_ss.eWoB, 0);
    add_ln_kernel<1,1><<<BB*QL, 256>>>(ao, ao2, w, ln1g, ln1b, x, xh, xl);

    // FFN: W1 full-grid; W2 split-K x2 across streams
    cudaStreamWaitEvent(0, g_ss.eW12, 0);
    mma_gemm<1,0,0,0><<<dim3(FF/128, (BB*QL)/128), 256, GSM_TOTAL>>>(
        xh, xl, w1h, w1l, nullptr, hhh, hhl, BB*QL, FF, EE);
    cudaEventRecord(g_ss.eW1d, 0);
    mma_gemm<0,0,FF,FF><<<dim3(EE/128, (BB*QL)/128), 256, GSM_TOTAL>>>(
        hhh, hhl, w2h, w2l, y, nullptr, nullptr, BB*QL, EE, FF/2);
    cudaStreamWaitEvent(s1, g_ss.eW1d, 0);
    mma_gemm<0,0,FF,FF><<<dim3(EE/128, (BB*QL)/128), 256, GSM_TOTAL, s1>>>(
        hhh + FF/2, hhl + FF/2, w2h + FF/2, w2l + FF/2,
        y2, nullptr, nullptr, BB*QL, EE, FF/2);
    cudaEventRecord(g_ss.eW2B, s1);
    cudaStreamWaitEvent(0, g_ss.eW2B, 0);
    add_ln_kernel<0,1><<<BB*QL, 256>>>(y, y2, x, ln2g, ln2b, out, nullptr, nullptr);
}

// round 16
// speedup vs baseline: 1.0206x; 1.0206x over previous
#include <cuda_runtime.h>
#include <cuda_bf16.h>
#include <math.h>
#include <stdint.h>

#define BB 2
#define QL 1024
#define ML 1024
#define KL 2048
#define EE 1024
#define HH 16
#define DH 64
#define FF 4096

typedef __nv_bfloat16 bf16;

// ---------------- scratch (static device globals) ---------------------------
__device__ float g_ao [BB*QL*EE];
__device__ float g_ao2[BB*QL*EE];
__device__ float g_x  [BB*QL*EE];
__device__ float g_y  [BB*QL*EE];
__device__ float g_y2 [BB*QL*EE];

__device__ bf16 g_cat_h[BB*KL*EE], g_cat_l[BB*KL*EE];
__device__ bf16 g_r_h  [KL*EE],    g_r_l  [KL*EE];
__device__ bf16 g_q_h  [BB*QL*EE], g_q_l  [BB*QL*EE];
__device__ bf16 g_k_h  [BB*KL*EE], g_k_l  [BB*KL*EE];
__device__ bf16 g_v_h  [BB*KL*EE], g_v_l  [BB*KL*EE];
__device__ bf16 g_rpj_h[KL*EE],    g_rpj_l[KL*EE];
__device__ bf16 g_att_h[BB*QL*EE], g_att_l[BB*QL*EE];
__device__ bf16 g_x_h  [BB*QL*EE], g_x_l  [BB*QL*EE];
__device__ bf16 g_hh_h [BB*QL*FF], g_hh_l [BB*QL*FF];
__device__ bf16 g_Wq_h[EE*EE], g_Wq_l[EE*EE];
__device__ bf16 g_Wk_h[EE*EE], g_Wk_l[EE*EE];
__device__ bf16 g_Wv_h[EE*EE], g_Wv_l[EE*EE];
__device__ bf16 g_Wr_h[EE*EE], g_Wr_l[EE*EE];
__device__ bf16 g_Wo_h[EE*EE], g_Wo_l[EE*EE];
__device__ bf16 g_W1_h[FF*EE], g_W1_l[FF*EE];
__device__ bf16 g_W2_h[EE*FF], g_W2_l[EE*FF];

// ---------------- persistent streams/events (host-side, created pre-run) ----
struct StreamSet {
    cudaStream_t s1, s2, s3;
    cudaEvent_t e0, eCat, eW, eV, eQ, eRg, eW12, eAtt, eWoB, eW1d, eW2B;
    StreamSet() {
        cudaStreamCreateWithFlags(&s1, cudaStreamNonBlocking);
        cudaStreamCreateWithFlags(&s2, cudaStreamNonBlocking);
        cudaStreamCreateWithFlags(&s3, cudaStreamNonBlocking);
        cudaEventCreateWithFlags(&e0,   cudaEventDisableTiming);
        cudaEventCreateWithFlags(&eCat, cudaEventDisableTiming);
        cudaEventCreateWithFlags(&eW,   cudaEventDisableTiming);
        cudaEventCreateWithFlags(&eV,   cudaEventDisableTiming);
        cudaEventCreateWithFlags(&eQ,   cudaEventDisableTiming);
        cudaEventCreateWithFlags(&eRg,  cudaEventDisableTiming);
        cudaEventCreateWithFlags(&eW12, cudaEventDisableTiming);
        cudaEventCreateWithFlags(&eAtt, cudaEventDisableTiming);
        cudaEventCreateWithFlags(&eWoB, cudaEventDisableTiming);
        cudaEventCreateWithFlags(&eW1d, cudaEventDisableTiming);
        cudaEventCreateWithFlags(&eW2B, cudaEventDisableTiming);
    }
};
static StreamSet g_ss;

// ---------------- helpers ----------------------------------------------------
__device__ __forceinline__ uint32_t smem_u32(const void* p) {
    uint32_t a;
    asm("{ .reg .u64 t; cvta.to.shared.u64 t, %1; cvt.u32.u64 %0, t; }"
        : "=r"(a) : "l"(p));
    return a;
}
__device__ __forceinline__ void split2(float v, bf16& h, bf16& l) {
    h = __float2bfloat16(v);
    l = __float2bfloat16(v - __bfloat162float(h));
}
__device__ __forceinline__ void ldsm4(uint32_t& r0, uint32_t& r1,
                                      uint32_t& r2, uint32_t& r3, uint32_t addr) {
    asm volatile("ldmatrix.sync.aligned.m8n8.x4.shared.b16 {%0,%1,%2,%3}, [%4];"
        : "=r"(r0), "=r"(r1), "=r"(r2), "=r"(r3) : "r"(addr));
}
__device__ __forceinline__ void ldsm4t(uint32_t& r0, uint32_t& r1,
                                       uint32_t& r2, uint32_t& r3, uint32_t addr) {
    asm volatile("ldmatrix.sync.aligned.m8n8.x4.trans.shared.b16 {%0,%1,%2,%3}, [%4];"
        : "=r"(r0), "=r"(r1), "=r"(r2), "=r"(r3) : "r"(addr));
}
__device__ __forceinline__ void mma16816(float* d, const uint32_t* a, const uint32_t* b) {
    asm volatile(
        "mma.sync.aligned.m16n8k16.row.col.f32.bf16.bf16.f32 "
        "{%0,%1,%2,%3}, {%4,%5,%6,%7}, {%8,%9}, {%0,%1,%2,%3};"
        : "+f"(d[0]), "+f"(d[1]), "+f"(d[2]), "+f"(d[3])
        : "r"(a[0]), "r"(a[1]), "r"(a[2]), "r"(a[3]), "r"(b[0]), "r"(b[1]));
}
__device__ __forceinline__ void cpa16(uint32_t d, const void* s) {
    asm volatile("cp.async.cg.shared.global [%0], [%1], 16;" :: "r"(d), "l"(s));
}
__device__ __forceinline__ void cpa16z(uint32_t d, const void* s, int sz) {
    asm volatile("cp.async.cg.shared.global [%0], [%1], 16, %2;"
                 :: "r"(d), "l"(s), "r"(sz));
}
#define CPA_COMMIT() asm volatile("cp.async.commit_group;")
template<int N> __device__ __forceinline__ void cpa_wait() {
    asm volatile("cp.async.wait_group %0;" :: "n"(N));
}

// ---------------- conversion kernels ----------------------------------------
__global__ __launch_bounds__(256) void concat_convert_kernel(
    const float* __restrict__ member, const float* __restrict__ w,
    bf16* __restrict__ dh, bf16* __restrict__ dl)
{
    int idx = blockIdx.x * 256 + threadIdx.x;
    int fidx = idx * 4;
    int b   = fidx / (KL*EE);
    int rem = fidx % (KL*EE);
    int s   = rem / EE;
    int e   = rem % EE;
    float4 v;
    if (s < ML) v = *(const float4*)&member[(size_t)(b*ML + s)*EE + e];
    else        v = *(const float4*)&w[(size_t)(b*QL + (s-ML))*EE + e];
    bf16 h0,l0,h1,l1,h2,l2,h3,l3;
    split2(v.x,h0,l0); split2(v.y,h1,l1); split2(v.z,h2,l2); split2(v.w,h3,l3);
    __nv_bfloat162 hp0, hp1, lp0, lp1;
    hp0.x=h0; hp0.y=h1; hp1.x=h2; hp1.y=h3;
    lp0.x=l0; lp0.y=l1; lp1.x=l2; lp1.y=l3;
    ((__nv_bfloat162*)dh)[idx*2]   = hp0; ((__nv_bfloat162*)dh)[idx*2+1] = hp1;
    ((__nv_bfloat162*)dl)[idx*2]   = lp0; ((__nv_bfloat162*)dl)[idx*2+1] = lp1;
}

__global__ __launch_bounds__(256) void convert_split_kernel(
    const float* __restrict__ s, bf16* __restrict__ dh, bf16* __restrict__ dl)
{
    int idx = blockIdx.x * 256 + threadIdx.x;
    float4 v = ((const float4*)s)[idx];
    bf16 h0,l0,h1,l1,h2,l2,h3,l3;
    split2(v.x,h0,l0); split2(v.y,h1,l1); split2(v.z,h2,l2); split2(v.w,h3,l3);
    __nv_bfloat162 hp0, hp1, lp0, lp1;
    hp0.x=h0; hp0.y=h1; hp1.x=h2; hp1.y=h3;
    lp0.x=l0; lp0.y=l1; lp1.x=l2; lp1.y=l3;
    ((__nv_bfloat162*)dh)[idx*2]   = hp0; ((__nv_bfloat162*)dh)[idx*2+1] = hp1;
    ((__nv_bfloat162*)dl)[idx*2]   = lp0; ((__nv_bfloat162*)dl)[idx*2+1] = lp1;
}

struct TC5 { const float* s[5]; bf16* dh[5]; bf16* dl[5]; };

__global__ void transpose_convert5_kernel(TC5 p)   // 5x square EExEE
{
    __shared__ float t[32][33];
    const float* s = p.s[blockIdx.z];
    bf16* dh = p.dh[blockIdx.z];
    bf16* dl = p.dl[blockIdx.z];
    int n0 = blockIdx.x * 32, k0 = blockIdx.y * 32;
    int tx = threadIdx.x, ty = threadIdx.y;
    #pragma unroll
    for (int i = 0; i < 4; i++)
        t[ty + i*8][tx] = s[(size_t)(k0 + ty + i*8)*EE + n0 + tx];
    __syncthreads();
    #pragma unroll
    for (int i = 0; i < 4; i++) {
        float v = t[tx][ty + i*8];
        bf16 h, l; split2(v, h, l);
        size_t o = (size_t)(n0 + ty + i*8)*EE + k0 + tx;
        dh[o] = h; dl[o] = l;
    }
}

__global__ void transpose_convert_kernel(
    const float* __restrict__ s, bf16* __restrict__ dh, bf16* __restrict__ dl,
    int K, int N)
{
    __shared__ float t[32][33];
    int n0 = blockIdx.x * 32, k0 = blockIdx.y * 32;
    int tx = threadIdx.x, ty = threadIdx.y;
    #pragma unroll
    for (int i = 0; i < 4; i++)
        t[ty + i*8][tx] = s[(size_t)(k0 + ty + i*8)*N + n0 + tx];
    __syncthreads();
    #pragma unroll
    for (int i = 0; i < 4; i++) {
        float v = t[tx][ty + i*8];
        bf16 h, l; split2(v, h, l);
        size_t o = (size_t)(n0 + ty + i*8)*K + k0 + tx;
        dh[o] = h; dl[o] = l;
    }
}

// ---------------- bf16x3 warp-MMA GEMM (cp.async double-buffered) -----------
#define SROW     40
#define OPELEMS  (128*SROW)
#define OPBYTES  (OPELEMS*2)
#define BUFELEMS (4*OPELEMS)
#define BUFBYTES (BUFELEMS*2)
#define GSM_TOTAL (2*BUFBYTES)

// EPI: 0 = fp32 store, 1 = relu + split bf16, 2 = split bf16
// REMAP: A rows remapped grow -> (grow/QL)*KL + ML + grow%QL  (Q-from-cat)
// LDA/LDB: compile-time row strides; 0 => use K (constant-folded, no extra regs)
template<int EPI, int REMAP, int LDA, int LDB>
__global__ __launch_bounds__(256, 2) void mma_gemm(
    const bf16* __restrict__ Ah, const bf16* __restrict__ Al,
    const bf16* __restrict__ Bh, const bf16* __restrict__ Bl,
    float* __restrict__ Cf, bf16* __restrict__ Ch, bf16* __restrict__ Cl,
    int M, int N, int K)
{
    extern __shared__ bf16 smem[];
    const int tid = threadIdx.x, wid = tid >> 5, lane = tid & 31;
    const int row0 = blockIdx.y * 128, col0 = blockIdx.x * 128;
    const int wm = wid & 1, wn = wid >> 1;
    const uint32_t sbase0 = smem_u32(smem);
    const int lda = LDA ? LDA : K;
    const int ldb = LDB ? LDB : K;

    float acc[4][4][4];
    #pragma unroll
    for (int mt = 0; mt < 4; mt++)
        #pragma unroll
        for (int nt = 0; nt < 4; nt++)
            #pragma unroll
            for (int u = 0; u < 4; u++) acc[mt][nt][u] = 0.f;

    const int nc = K >> 5;
    const int r0q = tid >> 2, c0q = (tid & 3) * 8;
    const int r1q = r0q + 64;

    size_t aR0, aR1;
    if (REMAP) {
        const int g0 = row0 + r0q, g1 = row0 + r1q;
        aR0 = ((size_t)(g0 >> 10)*KL + ML + (g0 & 1023)) * (size_t)lda;
        aR1 = ((size_t)(g1 >> 10)*KL + ML + (g1 & 1023)) * (size_t)lda;
    } else {
        aR0 = (size_t)(row0 + r0q) * lda;
        aR1 = (size_t)(row0 + r1q) * lda;
    }
    const size_t bR0 = (size_t)(col0 + r0q) * ldb;
    const size_t bR1 = (size_t)(col0 + r1q) * ldb;
    const uint32_t s0b = (uint32_t)(r0q*80 + c0q*2);
    const uint32_t s1b = (uint32_t)(r1q*80 + c0q*2);

    auto issue = [&](int c) {
        const uint32_t d = sbase0 + (uint32_t)(c & 1) * BUFBYTES;
        const size_t k0 = (size_t)(c * 32) + c0q;
        cpa16(d + s0b,             Ah + aR0 + k0);
        cpa16(d + s0b + OPBYTES,   Al + aR0 + k0);
        cpa16(d + s0b + 2*OPBYTES, Bh + bR0 + k0);
        cpa16(d + s0b + 3*OPBYTES, Bl + bR0 + k0);
        cpa16(d + s1b,             Ah + aR1 + k0);
        cpa16(d + s1b + OPBYTES,   Al + aR1 + k0);
        cpa16(d + s1b + 2*OPBYTES, Bh + bR1 + k0);
        cpa16(d + s1b + 3*OPBYTES, Bl + bR1 + k0);
        CPA_COMMIT();
    };

    issue(0);

    const uint32_t a_row_off = (uint32_t)(wm*64 + (lane & 15)) * 80
                             + (uint32_t)(lane >> 4) * 16;
    const uint32_t b_row_off = 2*OPBYTES
                             + (uint32_t)(wn*32 + (lane & 7) + ((lane >> 4) & 1)*8) * 80
                             + (uint32_t)((lane >> 3) & 1) * 16;

    for (int c = 0; c < nc; c++) {
        cpa_wait<0>();
        __syncthreads();
        if (c + 1 < nc) issue(c + 1);

        const uint32_t sb = sbase0 + (uint32_t)(c & 1) * BUFBYTES;
        #pragma unroll
        for (int ks = 0; ks < 2; ks++) {
            uint32_t ah[4][4], al[4][4], bh[4][2], bl[4][2];
            const uint32_t abase = sb + a_row_off + ks*32;
            #pragma unroll
            for (int mt = 0; mt < 4; mt++) {
                const uint32_t ad = abase + mt*(16*80);
                ldsm4(ah[mt][0], ah[mt][1], ah[mt][2], ah[mt][3], ad);
                ldsm4(al[mt][0], al[mt][1], al[mt][2], al[mt][3], ad + OPBYTES);
            }
            const uint32_t bbase = sb + b_row_off + ks*32;
            #pragma unroll
            for (int p = 0; p < 2; p++) {
                const uint32_t bd = bbase + p*(16*80);
                ldsm4(bh[2*p][0], bh[2*p][1], bh[2*p+1][0], bh[2*p+1][1], bd);
                ldsm4(bl[2*p][0], bl[2*p][1], bl[2*p+1][0], bl[2*p+1][1], bd + OPBYTES);
            }
            #pragma unroll
            for (int mt = 0; mt < 4; mt++)
                #pragma unroll
                for (int nt = 0; nt < 4; nt++) {
                    mma16816(acc[mt][nt], ah[mt], bh[nt]);
                    mma16816(acc[mt][nt], ah[mt], bl[nt]);
                    mma16816(acc[mt][nt], al[mt], bh[nt]);
                }
        }
    }

    const int er = lane >> 2, ec = (lane & 3) * 2;
    #pragma unroll
    for (int mt = 0; mt < 4; mt++) {
        #pragma unroll
        for (int nt = 0; nt < 4; nt++) {
            const int grow = row0 + wm*64 + mt*16 + er;
            const int gcol = col0 + wn*32 + nt*8 + ec;
            if (EPI == 0) {
                *(float2*)&Cf[(size_t)grow*N + gcol] =
                    make_float2(acc[mt][nt][0], acc[mt][nt][1]);
                *(float2*)&Cf[(size_t)(grow+8)*N + gcol] =
                    make_float2(acc[mt][nt][2], acc[mt][nt][3]);
            } else {
                float f0 = acc[mt][nt][0], f1 = acc[mt][nt][1];
                float f2 = acc[mt][nt][2], f3 = acc[mt][nt][3];
                if (EPI == 1) {
                    f0 = fmaxf(f0, 0.f); f1 = fmaxf(f1, 0.f);
                    f2 = fmaxf(f2, 0.f); f3 = fmaxf(f3, 0.f);
                }
                bf16 h0,l0,h1,l1,h2,l2,h3,l3;
                split2(f0,h0,l0); split2(f1,h1,l1);
                split2(f2,h2,l2); split2(f3,h3,l3);
                __nv_bfloat162 hp0, lp0, hp1, lp1;
                hp0.x=h0; hp0.y=h1; lp0.x=l0; lp0.y=l1;
                hp1.x=h2; hp1.y=h3; lp1.x=l2; lp1.y=l3;
                *(__nv_bfloat162*)&Ch[(size_t)grow*N + gcol]     = hp0;
                *(__nv_bfloat162*)&Cl[(size_t)grow*N + gcol]     = lp0;
                *(__nv_bfloat162*)&Ch[(size_t)(grow+8)*N + gcol] = hp1;
                *(__nv_bfloat162*)&Cl[(size_t)(grow+8)*N + gcol] = lp1;
            }
        }
    }
}

// ---------------- MMA flash attention: cp.async pipeline + rolling BDW ------
#define ASTR 144
#define A_QWH 0
#define A_QWL 9216
#define A_QRH 18432
#define A_QRL 27648
#define A_STG 36864
#define S_KH  0
#define S_KL  9216
#define S_VH  18432
#define S_VL  27648
#define S_RH  36864
#define S_RL  46080
#define STG_SZ 55296
#define A_SCR (A_STG + 2*STG_SZ)       // 147456
#define W_BDW 0
#define W_PH  8448
#define W_PL  10752
#define WSCR_SZ 13056
#define A_TOT (A_SCR + 4*WSCR_SZ)      // 199680

// one 64-col BDW half: D = Qr @ Rstage^T, stored at phys cols [pb, pb+64)
__device__ __forceinline__ void bdw_half(
    char* sm, uint32_t sb, uint32_t rbase, int pb,
    uint32_t aoff, uint32_t boff, uint32_t wscr, int er, int ec)
{
    float D[8][4];
    #pragma unroll
    for (int nt = 0; nt < 8; nt++)
        #pragma unroll
        for (int u = 0; u < 4; u++) D[nt][u] = 0.f;
    #pragma unroll
    for (int ks = 0; ks < 4; ks++) {
        uint32_t arh[4], arl[4];
        ldsm4(arh[0], arh[1], arh[2], arh[3], sb + A_QRH + aoff + ks*32);
        ldsm4(arl[0], arl[1], arl[2], arl[3], sb + A_QRL + aoff + ks*32);
        #pragma unroll
        for (int p = 0; p < 4; p++) {
            uint32_t bh4[4], bl4[4];
            const uint32_t ra = rbase + boff + (uint32_t)(p*16)*ASTR + ks*32;
            ldsm4(bh4[0], bh4[1], bh4[2], bh4[3], ra);
            ldsm4(bl4[0], bl4[1], bl4[2], bl4[3], ra + (S_RL - S_RH));
            mma16816(D[2*p],   arh, bh4);   mma16816(D[2*p],   arh, bl4);
            mma16816(D[2*p],   arl, bh4);
            mma16816(D[2*p+1], arh, bh4+2); mma16816(D[2*p+1], arh, bl4+2);
            mma16816(D[2*p+1], arl, bh4+2);
        }
    }
    float* bdw = (float*)(sm + wscr + W_BDW);
    #pragma unroll
    for (int nt = 0; nt < 8; nt++) {
        const int c = pb + nt*8 + ec;
        bdw[er*132 + c]       = D[nt][0];
        bdw[er*132 + c + 1]   = D[nt][1];
        bdw[(er+8)*132 + c]   = D[nt][2];
        bdw[(er+8)*132 + c+1] = D[nt][3];
    }
}

__global__ __launch_bounds__(128) void attn_mma_kernel(
    const bf16* __restrict__ Qh, const bf16* __restrict__ Ql,
    const bf16* __restrict__ Kh, const bf16* __restrict__ Kl,
    const bf16* __restrict__ Vh, const bf16* __restrict__ Vl,
    const bf16* __restrict__ Rh, const bf16* __restrict__ Rl,
    const float* __restrict__ rwb, const float* __restrict__ rrb,
    bf16* __restrict__ OHp, bf16* __restrict__ OLp)
{
    extern __shared__ char sm[];
    const uint32_t sb = smem_u32(sm);
    // longest-first scheduling: high i0 (most k-tiles) launches first
    const int i0 = (gridDim.x - 1 - blockIdx.x) * 64;
    const int h  = blockIdx.y, b = blockIdx.z;
    const int tid = threadIdx.x, w = tid >> 5, lane = tid & 31;

    // ---- load Q, add biases, split, store both variants ----
    #pragma unroll
    for (int it = 0; it < 4; it++) {
        int idx = tid + it*128;
        int row = idx >> 3, c8 = (idx & 7) * 8;
        const size_t g = (size_t)(b*QL + i0 + row)*EE + h*DH + c8;
        union { uint4 u; bf16 e[8]; } uh, ul;
        uh.u = *(const uint4*)(Qh + g);
        ul.u = *(const uint4*)(Ql + g);
        bf16* qwh = (bf16*)(sm + A_QWH + row*ASTR) + c8;
        bf16* qwl = (bf16*)(sm + A_QWL + row*ASTR) + c8;
        bf16* qrh = (bf16*)(sm + A_QRH + row*ASTR) + c8;
        bf16* qrl = (bf16*)(sm + A_QRL + row*ASTR) + c8;
        #pragma unroll
        for (int e = 0; e < 8; e++) {
            float q = __bfloat162float(uh.e[e]) + __bfloat162float(ul.e[e]);
            bf16 hh, ll;
            split2(q + rwb[h*DH + c8 + e], hh, ll); qwh[e] = hh; qwl[e] = ll;
            split2(q + rrb[h*DH + c8 + e], hh, ll); qrh[e] = hh; qrl[e] = ll;
        }
    }

    float O[8][4];
    #pragma unroll
    for (int nt = 0; nt < 8; nt++)
        #pragma unroll
        for (int u = 0; u < 4; u++) O[nt][u] = 0.f;
    float m_i[2] = {-INFINITY, -INFINITY}, l_i[2] = {0.f, 0.f};

    const uint32_t aoff = (uint32_t)(w*16 + (lane&15))*ASTR + ((lane>>4)&1)*16;
    const uint32_t boff = (uint32_t)((lane&7) + ((lane>>4)&1)*8)*ASTR + ((lane>>3)&1)*16;
    const uint32_t voff = (uint32_t)((lane&7) + ((lane>>3)&1)*8)*ASTR + ((lane>>4)&1)*16;
    const uint32_t poff = (uint32_t)(lane&15)*ASTR + ((lane>>4)&1)*16;
    const uint32_t wscr = A_SCR + w*WSCR_SZ;
    const int er = lane >> 2, ec = (lane & 3) * 2;
    const int lr0 = w*16 + er, lr1 = lr0 + 8;
    const int ig0 = i0 + lr0, ig1 = i0 + lr1;

    int njt = (i0 + 63 + ML)/64 + 1;
    if (njt > KL/64) njt = KL/64;
    const int rorg = 960 - i0;   // absolute r-index of physical BDW slot 0

    const int ldrow = tid >> 3, ldc8 = (tid & 7) * 8;

    // ---- prologue: R_low -> stage1 R area; tile0 -> stage0 ----
    #pragma unroll
    for (int it = 0; it < 4; it++) {
        int row = ldrow + it*16;
        int dg = rorg + row;                           // >= 0 always (i0<=960)
        const size_t g = (size_t)dg*EE + h*DH + ldc8;
        uint32_t d = sb + A_STG + STG_SZ + S_RH + row*ASTR + ldc8*2;
        cpa16(d,                 Rh + g);
        cpa16(d + (S_RL - S_RH), Rl + g);
    }
    {
        const uint32_t stg = sb + A_STG;               // stage 0
        #pragma unroll
        for (int it = 0; it < 4; it++) {
            int row = ldrow + it*16;
            const size_t g = (size_t)(b*KL + row)*EE + h*DH + ldc8;
            const uint32_t so = row*ASTR + ldc8*2;
            cpa16(stg + S_KH + so, Kh + g);
            cpa16(stg + S_KL + so, Kl + g);
            cpa16(stg + S_VH + so, Vh + g);
            cpa16(stg + S_VL + so, Vl + g);
            int dg = rorg + 64 + row;
            int ok = dg < KL;
            const size_t gr = (size_t)(ok ? dg : 0)*EE + h*DH + ldc8;
            cpa16z(stg + S_RH + so, Rh + gr, ok ? 16 : 0);
            cpa16z(stg + S_RL + so, Rl + gr, ok ? 16 : 0);
        }
    }
    CPA_COMMIT();
    cpa_wait<0>();
    __syncthreads();

    // prologue BDW (phys cols [0,64), from stage1 R)
    bdw_half(sm, sb, sb + A_STG + STG_SZ + S_RH, 0, aoff, boff, wscr, er, ec);

    for (int jt = 0; jt < njt; jt++) {
        const int j0 = jt * 64;
        __syncthreads();                       // all warps done with jt-1 (+ prologue BDW)
        if (jt + 1 < njt) {
            const uint32_t stg = sb + A_STG + ((jt+1)&1)*STG_SZ;
            const int jn = (jt+1)*64;
            #pragma unroll
            for (int it = 0; it < 4; it++) {
                int row = ldrow + it*16;
                const size_t g = (size_t)(b*KL + jn + row)*EE + h*DH + ldc8;
                const uint32_t so = row*ASTR + ldc8*2;
                cpa16(stg + S_KH + so, Kh + g);
                cpa16(stg + S_KL + so, Kl + g);
                cpa16(stg + S_VH + so, Vh + g);
                cpa16(stg + S_VL + so, Vl + g);
                int dg = rorg + 64*(jt+2) + row;
                int ok = dg < KL;
                const size_t gr = (size_t)(ok ? dg : 0)*EE + h*DH + ldc8;
                cpa16z(stg + S_RH + so, Rh + gr, ok ? 16 : 0);
                cpa16z(stg + S_RL + so, Rl + gr, ok ? 16 : 0);
            }
            CPA_COMMIT();
            cpa_wait<1>();
        } else {
            cpa_wait<0>();
        }
        __syncthreads();

        const uint32_t stg = sb + A_STG + (jt&1)*STG_SZ;

        // ---- BDW new half (64 cols) -> phys base alternates 64/0 ----
        bdw_half(sm, sb, stg + S_RH, (jt&1) ? 0 : 64, aoff, boff, wscr, er, ec);

        // ---- AC = Qw @ K^T ----
        float S[8][4];
        #pragma unroll
        for (int nt = 0; nt < 8; nt++)
            #pragma unroll
            for (int u = 0; u < 4; u++) S[nt][u] = 0.f;
        #pragma unroll
        for (int ks = 0; ks < 4; ks++) {
            uint32_t awh[4], awl[4];
            ldsm4(awh[0], awh[1], awh[2], awh[3], sb + A_QWH + aoff + ks*32);
            ldsm4(awl[0], awl[1], awl[2], awl[3], sb + A_QWL + aoff + ks*32);
            #pragma unroll
            for (int p = 0; p < 4; p++) {
                uint32_t bh4[4], bl4[4];
                const uint32_t ka = stg + S_KH + boff + (uint32_t)(p*16)*ASTR + ks*32;
                ldsm4(bh4[0], bh4[1], bh4[2], bh4[3], ka);
                ldsm4(bl4[0], bl4[1], bl4[2], bl4[3], ka + (S_KL - S_KH));
                mma16816(S[2*p],   awh, bh4);   mma16816(S[2*p],   awh, bl4);
                mma16816(S[2*p],   awl, bh4);
                mma16816(S[2*p+1], awh, bh4+2); mma16816(S[2*p+1], awh, bl4+2);
                mma16816(S[2*p+1], awl, bh4+2);
            }
        }
        __syncwarp();

        // ---- gather rolling BDW diagonal, mask+scale, online softmax ----
        const float* bdw = (const float*)(sm + wscr + W_BDW);
        const int phase = (jt & 1) * 64;
        float mx0 = -INFINITY, mx1 = -INFINITY;
        #pragma unroll
        for (int nt = 0; nt < 8; nt++) {
            const int c = nt*8 + ec;
            float s00 = S[nt][0] + bdw[er*132     + ((c   - lr0 + 63 + phase) & 127)];
            float s01 = S[nt][1] + bdw[er*132     + ((c+1 - lr0 + 63 + phase) & 127)];
            float s10 = S[nt][2] + bdw[(er+8)*132 + ((c   - lr1 + 63 + phase) & 127)];
            float s11 = S[nt][3] + bdw[(er+8)*132 + ((c+1 - lr1 + 63 + phase) & 127)];
            const int jg = j0 + c;
            s00 = (jg   > ig0 + ML) ? -1e30f : s00 * 0.03125f;
            s01 = (jg+1 > ig0 + ML) ? -1e30f : s01 * 0.03125f;
            s10 = (jg   > ig1 + ML) ? -1e30f : s10 * 0.03125f;
            s11 = (jg+1 > ig1 + ML) ? -1e30f : s11 * 0.03125f;
            S[nt][0] = s00; S[nt][1] = s01; S[nt][2] = s10; S[nt][3] = s11;
            mx0 = fmaxf(mx0, fmaxf(s00, s01));
            mx1 = fmaxf(mx1, fmaxf(s10, s11));
        }
        mx0 = fmaxf(mx0, __shfl_xor_sync(0xffffffffu, mx0, 1));
        mx0 = fmaxf(mx0, __shfl_xor_sync(0xffffffffu, mx0, 2));
        mx1 = fmaxf(mx1, __shfl_xor_sync(0xffffffffu, mx1, 1));
        mx1 = fmaxf(mx1, __shfl_xor_sync(0xffffffffu, mx1, 2));
        const float mn0 = fmaxf(m_i[0], mx0), mn1 = fmaxf(m_i[1], mx1);
        const float sf0 = __expf(m_i[0] - mn0), sf1 = __expf(m_i[1] - mn1);
        m_i[0] = mn0; m_i[1] = mn1;

        bf16* pph = (bf16*)(sm + wscr + W_PH);
        bf16* ppl = (bf16*)(sm + wscr + W_PL);
        float ps0 = 0.f, ps1 = 0.f;
        #pragma unroll
        for (int nt = 0; nt < 8; nt++) {
            const int c = nt*8 + ec;
            float p00 = __expf(S[nt][0] - mn0);
            float p01 = __expf(S[nt][1] - mn0);
            float p10 = __expf(S[nt][2] - mn1);
            float p11 = __expf(S[nt][3] - mn1);
            ps0 += p00 + p01; ps1 += p10 + p11;
            bf16 h0,l0,h1,l1;
            __nv_bfloat162 hp, lp;
            split2(p00,h0,l0); split2(p01,h1,l1);
            hp.x=h0; hp.y=h1; lp.x=l0; lp.y=l1;
            *(__nv_bfloat162*)(pph + er*72 + c) = hp;
            *(__nv_bfloat162*)(ppl + er*72 + c) = lp;
            split2(p10,h0,l0); split2(p11,h1,l1);
            hp.x=h0; hp.y=h1; lp.x=l0; lp.y=l1;
            *(__nv_bfloat162*)(pph + (er+8)*72 + c) = hp;
            *(__nv_bfloat162*)(ppl + (er+8)*72 + c) = lp;
        }
        ps0 += __shfl_xor_sync(0xffffffffu, ps0, 1);
        ps0 += __shfl_xor_sync(0xffffffffu, ps0, 2);
        ps1 += __shfl_xor_sync(0xffffffffu, ps1, 1);
        ps1 += __shfl_xor_sync(0xffffffffu, ps1, 2);
        l_i[0] = l_i[0]*sf0 + ps0;
        l_i[1] = l_i[1]*sf1 + ps1;
        #pragma unroll
        for (int nt = 0; nt < 8; nt++) {
            O[nt][0] *= sf0; O[nt][1] *= sf0;
            O[nt][2] *= sf1; O[nt][3] *= sf1;
        }
        __syncwarp();

        // ---- O += P @ V ----
        #pragma unroll
        for (int ks = 0; ks < 4; ks++) {
            uint32_t ph4[4], pl4[4];
            ldsm4(ph4[0], ph4[1], ph4[2], ph4[3], sb + wscr + W_PH + poff + ks*32);
            ldsm4(pl4[0], pl4[1], pl4[2], pl4[3], sb + wscr + W_PL + poff + ks*32);
            #pragma unroll
            for (int p = 0; p < 4; p++) {
                uint32_t vh4[4], vl4[4];
                const uint32_t va = stg + S_VH + voff + (uint32_t)(ks*16)*ASTR + p*32;
                ldsm4t(vh4[0], vh4[1], vh4[2], vh4[3], va);
                ldsm4t(vl4[0], vl4[1], vl4[2], vl4[3], va + (S_VL - S_VH));
                mma16816(O[2*p],   ph4, vh4);   mma16816(O[2*p],   ph4, vl4);
                mma16816(O[2*p],   pl4, vh4);
                mma16816(O[2*p+1], ph4, vh4+2); mma16816(O[2*p+1], ph4, vl4+2);
                mma16816(O[2*p+1], pl4, vh4+2);
            }
        }
    }

    // ---- epilogue: normalize + split store ----
    const float inv0 = 1.0f / l_i[0], inv1 = 1.0f / l_i[1];
    #pragma unroll
    for (int nt = 0; nt < 8; nt++) {
        const int c = nt*8 + ec;
        const size_t g0 = (size_t)(b*QL + ig0)*EE + h*DH + c;
        const size_t g1 = (size_t)(b*QL + ig1)*EE + h*DH + c;
        bf16 h0,l0,h1,l1;
        __nv_bfloat162 hp, lp;
        split2(O[nt][0]*inv0, h0, l0); split2(O[nt][1]*inv0, h1, l1);
        hp.x=h0; hp.y=h1; lp.x=l0; lp.y=l1;
        *(__nv_bfloat162*)(OHp + g0) = hp;
        *(__nv_bfloat162*)(OLp + g0) = lp;
        split2(O[nt][2]*inv1, h0, l0); split2(O[nt][3]*inv1, h1, l1);
        hp.x=h0; hp.y=h1; lp.x=l0; lp.y=l1;
        *(__nv_bfloat162*)(OHp + g1) = hp;
        *(__nv_bfloat162*)(OLp + g1) = lp;
    }
}

// ---------------- residual add + LayerNorm ----------------------------------
// TWO=1: sums a + a2 (split-K partials) + residual
template<int WB, int TWO>
__global__ __launch_bounds__(256) void add_ln_kernel(
    const float* __restrict__ a, const float* __restrict__ a2,
    const float* __restrict__ res,
    const float* __restrict__ g, const float* __restrict__ bt,
    float* __restrict__ out, bf16* __restrict__ oh, bf16* __restrict__ ol)
{
    __shared__ float red[256];
    const int row = blockIdx.x;
    const int tid = threadIdx.x;
    const size_t base = (size_t)row * EE;

    float v[4];
    #pragma unroll
    for (int u = 0; u < 4; u++) {
        v[u] = a[base + u*256 + tid] + res[base + u*256 + tid];
        if (TWO) v[u] += a2[base + u*256 + tid];
    }

    float s = v[0] + v[1] + v[2] + v[3];
    red[tid] = s; __syncthreads();
    for (int off = 128; off > 0; off >>= 1) {
        if (tid < off) red[tid] += red[tid + off];
        __syncthreads();
    }
    const float mu = red[0] * (1.0f / EE);
    __syncthreads();

    float d = 0.f;
    #pragma unroll
    for (int u = 0; u < 4; u++) { float t = v[u] - mu; d += t*t; }
    red[tid] = d; __syncthreads();
    for (int off = 128; off > 0; off >>= 1) {
        if (tid < off) red[tid] += red[tid + off];
        __syncthreads();
    }
    const float rs = rsqrtf(red[0] * (1.0f / EE) + 1e-3f);

    #pragma unroll
    for (int u = 0; u < 4; u++) {
        int c = u*256 + tid;
        float o = (v[u] - mu) * rs * g[c] + bt[c];
        out[base + c] = o;
        if (WB) {
            bf16 hh_, ll_; split2(o, hh_, ll_);
            oh[base + c] = hh_; ol[base + c] = ll_;
        }
    }
}

// ---------------- launch ----------------------------------------------------
extern "C" void kernel_launch(void* const* d_in, const int* in_sizes, int n_in,
                              void* d_out, int out_size)
{
    const float* w      = (const float*)d_in[0];
    const float* r      = (const float*)d_in[1];
    const float* member = (const float*)d_in[2];
    const float* Wq     = (const float*)d_in[4];
    const float* Wk     = (const float*)d_in[5];
    const float* Wv     = (const float*)d_in[6];
    const float* Wr     = (const float*)d_in[7];
    const float* Wo     = (const float*)d_in[8];
    const float* rwb    = (const float*)d_in[9];
    const float* rrb    = (const float*)d_in[10];
    const float* ln1g   = (const float*)d_in[11];
    const float* ln1b   = (const float*)d_in[12];
    const float* W1     = (const float*)d_in[13];
    const float* W2     = (const float*)d_in[14];
    const float* ln2g   = (const float*)d_in[15];
    const float* ln2b   = (const float*)d_in[16];
    float* out = (float*)d_out;

    float *ao,*ao2,*x,*y,*y2;
    cudaGetSymbolAddress((void**)&ao,  g_ao);
    cudaGetSymbolAddress((void**)&ao2, g_ao2);
    cudaGetSymbolAddress((void**)&x,   g_x);
    cudaGetSymbolAddress((void**)&y,   g_y);
    cudaGetSymbolAddress((void**)&y2,  g_y2);
    bf16 *cath,*catl,*rih,*ril,*atth,*attl,*xh,*xl,*hhh,*hhl;
    bf16 *qph,*qpl,*kph,*kpl,*vph,*vpl,*rph,*rpl;
    bf16 *wqh,*wql,*wkh,*wkl,*wvh,*wvl,*wrh,*wrl,*woh,*wol,*w1h,*w1l,*w2h,*w2l;
    cudaGetSymbolAddress((void**)&cath, g_cat_h); cudaGetSymbolAddress((void**)&catl, g_cat_l);
    cudaGetSymbolAddress((void**)&rih,  g_r_h);   cudaGetSymbolAddress((void**)&ril,  g_r_l);
    cudaGetSymbolAddress((void**)&qph,  g_q_h);   cudaGetSymbolAddress((void**)&qpl,  g_q_l);
    cudaGetSymbolAddress((void**)&kph,  g_k_h);   cudaGetSymbolAddress((void**)&kpl,  g_k_l);
    cudaGetSymbolAddress((void**)&vph,  g_v_h);   cudaGetSymbolAddress((void**)&vpl,  g_v_l);
    cudaGetSymbolAddress((void**)&rph,  g_rpj_h); cudaGetSymbolAddress((void**)&rpl,  g_rpj_l);
    cudaGetSymbolAddress((void**)&atth, g_att_h); cudaGetSymbolAddress((void**)&attl, g_att_l);
    cudaGetSymbolAddress((void**)&xh,   g_x_h);   cudaGetSymbolAddress((void**)&xl,   g_x_l);
    cudaGetSymbolAddress((void**)&hhh,  g_hh_h);  cudaGetSymbolAddress((void**)&hhl,  g_hh_l);
    cudaGetSymbolAddress((void**)&wqh,  g_Wq_h);  cudaGetSymbolAddress((void**)&wql,  g_Wq_l);
    cudaGetSymbolAddress((void**)&wkh,  g_Wk_h);  cudaGetSymbolAddress((void**)&wkl,  g_Wk_l);
    cudaGetSymbolAddress((void**)&wvh,  g_Wv_h);  cudaGetSymbolAddress((void**)&wvl,  g_Wv_l);
    cudaGetSymbolAddress((void**)&wrh,  g_Wr_h);  cudaGetSymbolAddress((void**)&wrl,  g_Wr_l);
    cudaGetSymbolAddress((void**)&woh,  g_Wo_h);  cudaGetSymbolAddress((void**)&wol,  g_Wo_l);
    cudaGetSymbolAddress((void**)&w1h,  g_W1_h);  cudaGetSymbolAddress((void**)&w1l,  g_W1_l);
    cudaGetSymbolAddress((void**)&w2h,  g_W2_h);  cudaGetSymbolAddress((void**)&w2l,  g_W2_l);

    cudaFuncSetAttribute((const void*)mma_gemm<0,0,0,0>,   cudaFuncAttributeMaxDynamicSharedMemorySize, GSM_TOTAL);
    cudaFuncSetAttribute((const void*)mma_gemm<1,0,0,0>,   cudaFuncAttributeMaxDynamicSharedMemorySize, GSM_TOTAL);
    cudaFuncSetAttribute((const void*)mma_gemm<2,0,0,0>,   cudaFuncAttributeMaxDynamicSharedMemorySize, GSM_TOTAL);
    cudaFuncSetAttribute((const void*)mma_gemm<2,1,0,0>,   cudaFuncAttributeMaxDynamicSharedMemorySize, GSM_TOTAL);
    cudaFuncSetAttribute((const void*)mma_gemm<0,0,EE,EE>, cudaFuncAttributeMaxDynamicSharedMemorySize, GSM_TOTAL);
    cudaFuncSetAttribute((const void*)mma_gemm<0,0,FF,FF>, cudaFuncAttributeMaxDynamicSharedMemorySize, GSM_TOTAL);
    cudaFuncSetAttribute((const void*)attn_mma_kernel, cudaFuncAttributeMaxDynamicSharedMemorySize, A_TOT);

    cudaStream_t s1 = g_ss.s1, s2 = g_ss.s2, s3 = g_ss.s3;

    // fork side streams into the capture
    cudaEventRecord(g_ss.e0, 0);
    cudaStreamWaitEvent(s1, g_ss.e0, 0);
    cudaStreamWaitEvent(s2, g_ss.e0, 0);
    cudaStreamWaitEvent(s3, g_ss.e0, 0);

    // stream 0: concat conversion
    concat_convert_kernel<<<BB*KL*EE/4/256, 256>>>(member, w, cath, catl);
    cudaEventRecord(g_ss.eCat, 0);

    // s1: square weight transposes
    {
        TC5 p;
        p.s[0]=Wq; p.dh[0]=wqh; p.dl[0]=wql;
        p.s[1]=Wk; p.dh[1]=wkh; p.dl[1]=wkl;
        p.s[2]=Wv; p.dh[2]=wvh; p.dl[2]=wvl;
        p.s[3]=Wr; p.dh[3]=wrh; p.dl[3]=wrl;
        p.s[4]=Wo; p.dh[4]=woh; p.dl[4]=wol;
        transpose_convert5_kernel<<<dim3(EE/32, EE/32, 5), dim3(32,8), 0, s1>>>(p);
    }
    cudaEventRecord(g_ss.eW, s1);

    // s2: r conversion, then FFN weight transposes
    convert_split_kernel<<<KL*EE/4/256, 256, 0, s2>>>(r, rih, ril);
    transpose_convert_kernel<<<dim3(FF/32, EE/32), dim3(32,8), 0, s2>>>(W1, w1h, w1l, EE, FF);
    transpose_convert_kernel<<<dim3(EE/32, FF/32), dim3(32,8), 0, s2>>>(W2, w2h, w2l, FF, EE);
    cudaEventRecord(g_ss.eW12, s2);

    // projections spread over 4 streams
    cudaStreamWaitEvent(0, g_ss.eW, 0);
    mma_gemm<2,0,0,0><<<dim3(EE/128, (BB*KL)/128), 256, GSM_TOTAL>>>(
        cath, catl, wkh, wkl, nullptr, kph, kpl, BB*KL, EE, EE);

    cudaStreamWaitEvent(s1, g_ss.eCat, 0);
    mma_gemm<2,0,0,0><<<dim3(EE/128, (BB*KL)/128), 256, GSM_TOTAL, s1>>>(
        cath, catl, wvh, wvl, nullptr, vph, vpl, BB*KL, EE, EE);
    cudaEventRecord(g_ss.eV, s1);

    cudaStreamWaitEvent(s3, g_ss.eCat, 0);
    cudaStreamWaitEvent(s3, g_ss.eW, 0);
    mma_gemm<2,1,0,0><<<dim3(EE/128, (BB*QL)/128), 256, GSM_TOTAL, s3>>>(
        cath, catl, wqh, wql, nullptr, qph, qpl, BB*QL, EE, EE);
    cudaEventRecord(g_ss.eQ, s3);

    cudaStreamWaitEvent(s2, g_ss.eW, 0);
    mma_gemm<2,0,0,0><<<dim3(EE/128, KL/128), 256, GSM_TOTAL, s2>>>(
        rih, ril, wrh, wrl, nullptr, rph, rpl, KL, EE, EE);
    cudaEventRecord(g_ss.eRg, s2);

    // join, then attention on stream 0
    cudaStreamWaitEvent(0, g_ss.eV, 0);
    cudaStreamWaitEvent(0, g_ss.eQ, 0);
    cudaStreamWaitEvent(0, g_ss.eRg, 0);
    attn_mma_kernel<<<dim3(QL/64, HH, BB), 128, A_TOT>>>(
        qph, qpl, kph, kpl, vph, vpl, rph, rpl, rwb, rrb, atth, attl);
    cudaEventRecord(g_ss.eAtt, 0);

    // output projection: split-K x2 across streams (full-chip occupancy)
    mma_gemm<0,0,EE,EE><<<dim3(EE/128, (BB*QL)/128), 256, GSM_TOTAL>>>(
        atth, attl, woh, wol, ao, nullptr, nullptr, BB*QL, EE, EE/2);
    cudaStreamWaitEvent(s1, g_ss.eAtt, 0);
    mma_gemm<0,0,EE,EE><<<dim3(EE/128, (BB*QL)/128), 256, GSM_TOTAL, s1>>>(
        atth + EE/2, attl + EE/2, woh + EE/2, wol + EE/2,
        ao2, nullptr, nullptr, BB*QL, EE, EE/2);
    cudaEventRecord(g_ss.eWoB, s1);
    cudaStreamWaitEvent(0, g_ss.eWoB, 0);
    add_ln_kernel<1,1><<<BB*QL, 256>>>(ao, ao2, w, ln1g, ln1b, x, xh, xl);

    // FFN: W1 full-grid; W2 split-K x2 across streams
    cudaStreamWaitEvent(0, g_ss.eW12, 0);
    mma_gemm<1,0,0,0><<<dim3(FF/128, (BB*QL)/128), 256, GSM_TOTAL>>>(
        xh, xl, w1h, w1l, nullptr, hhh, hhl, BB*QL, FF, EE);
    cudaEventRecord(g_ss.eW1d, 0);
    mma_gemm<0,0,FF,FF><<<dim3(EE/128, (BB*QL)/128), 256, GSM_TOTAL>>>(
        hhh, hhl, w2h, w2l, y, nullptr, nullptr, BB*QL, EE, FF/2);
    cudaStreamWaitEvent(s1, g_ss.eW1d, 0);
    mma_gemm<0,0,FF,FF><<<dim3(EE/128, (BB*QL)/128), 256, GSM_TOTAL, s1>>>(
        hhh + FF/2, hhl + FF/2, w2h + FF/2, w2l + FF/2,
        y2, nullptr, nullptr, BB*QL, EE, FF/2);
    cudaEventRecord(g_ss.eW2B, s1);
    cudaStreamWaitEvent(0, g_ss.eW2B, 0);
    add_ln_kernel<0,1><<<BB*QL, 256>>>(y, y2, x, ln2g, ln2b, out, nullptr, nullptr);
}